// round 9
// baseline (speedup 1.0000x reference)
#include <cuda_runtime.h>
#include <cuda_fp16.h>
#include <math.h>
#include <stdint.h>

#define BB 32
#define LL 2048
#define PP 512
#define KK 64
#define NT (BB*LL)   // 65536 tokens
#define VOCAB 50257

// ---- scratch (device globals: no allocation allowed) ----
__device__ __align__(16) float g_G[(size_t)NT*KK];     // cosine sims, 16 MB
__device__ __align__(16) float g_VWx[(size_t)NT*KK];   // per-token e . f2w^T, 16 MB
__device__ float g_t[NT];                              // max-over-k pre-softmax
__device__ float g_beta[NT];                           // softmax weights (incl. 1/L)
// fragments pre-baked into m16n8k16 B layout (fp16):
// [c16 (32)][ntile (8)][lane (32)] -> uint2 {b0, b1}
__device__ __align__(16) uint2 g_Bfrag[32*8*32];       // normalized centroids
__device__ __align__(16) uint2 g_Wfrag[32*8*32];       // f2_w

// ============================================================
// helpers
// ============================================================
__device__ __forceinline__ void mma16816(float* d, const uint32_t* a, const uint32_t* b) {
    asm volatile(
        "mma.sync.aligned.m16n8k16.row.col.f32.f16.f16.f32 "
        "{%0,%1,%2,%3}, {%4,%5,%6,%7}, {%8,%9}, {%0,%1,%2,%3};"
        : "+f"(d[0]), "+f"(d[1]), "+f"(d[2]), "+f"(d[3])
        : "r"(a[0]), "r"(a[1]), "r"(a[2]), "r"(a[3]), "r"(b[0]), "r"(b[1]));
}
#define LDSM4(r, addr) \
    asm volatile("ldmatrix.sync.aligned.m8n8.x4.shared.b16 {%0,%1,%2,%3}, [%4];" \
        : "=r"((r)[0]), "=r"((r)[1]), "=r"((r)[2]), "=r"((r)[3]) : "r"(addr))

// ============================================================
// K0: one-shot setup. CTA n (64): centroid-n inv norm, B/W fragments,
// out-bias init.
// ============================================================
__global__ __launch_bounds__(256) void k_setup(const float* __restrict__ C,
                                               const float* __restrict__ W,
                                               const float* __restrict__ f2b,
                                               float* __restrict__ out) {
    int n = blockIdx.x;
    int tid = threadIdx.x;
    __shared__ float ws[8];
    __shared__ float s_inv;

    float s = 0.f;
    for (int p = tid; p < PP; p += 256) { float v = C[n*PP + p]; s += v*v; }
    for (int o = 16; o; o >>= 1) s += __shfl_xor_sync(0xffffffffu, s, o);
    if ((tid & 31) == 0) ws[tid >> 5] = s;
    __syncthreads();
    if (tid == 0)
        s_inv = rsqrtf(ws[0]+ws[1]+ws[2]+ws[3]+ws[4]+ws[5]+ws[6]+ws[7]);
    __syncthreads();
    float inv = s_inv;

    // fragment positions owned by centroid n: item = c16*4 + j  (128 items)
    int nt = n >> 3;
    int lbase = (n & 7) * 4;
    for (int item = tid; item < 128; item += 256) {
        int c16 = item >> 2, j = item & 3;
        int k = c16*16 + j*2;
        int fidx = c16*256 + nt*32 + lbase + j;
        __half2 b0 = __floats2half2_rn(C[n*PP + k]     * inv, C[n*PP + k + 1] * inv);
        __half2 b1 = __floats2half2_rn(C[n*PP + k + 8] * inv, C[n*PP + k + 9] * inv);
        g_Bfrag[fidx] = make_uint2(*(uint32_t*)&b0, *(uint32_t*)&b1);
        __half2 w0 = __floats2half2_rn(W[n*PP + k],     W[n*PP + k + 1]);
        __half2 w1 = __floats2half2_rn(W[n*PP + k + 8], W[n*PP + k + 9]);
        g_Wfrag[fidx] = make_uint2(*(uint32_t*)&w0, *(uint32_t*)&w1);
    }
    // out init: 2048 total = 64 CTAs x 32
    if (tid < 32) out[n*32 + tid] = f2b[(n*32 + tid) & 63];
}

// ============================================================
// K1: fused gathered GEMM: G = norm(emb) @ Chat^T ; VWx = emb @ f2w^T
// 512 thr (16 warps), 128 tokens/CTA, K=512 in 8 chunks of 64.
// Warps 0-7: centroid MMAs (G). Warps 8-15: f2w MMAs (VWx).
// Gather: warp w loads rows w*8..w*8+7 (16 lanes per row, reg prefetch).
// ============================================================
#define ASTRH 72   // fp16 row stride (144B)

__global__ __launch_bounds__(512) void k_cosine(const int* __restrict__ x,
                                                const float* __restrict__ V) {
    __shared__ __half Ah[2][128*ASTRH];        // 2 x 18432 B
    __shared__ const float* rowp[128];
    __shared__ float sqs[128];

    int tid = threadIdx.x;
    int w   = tid >> 5;
    int l   = tid & 31;
    int t0  = blockIdx.x * 128;

    if (tid < 128) rowp[tid] = V + (size_t)__ldg(&x[t0 + tid]) * PP;
    __syncthreads();

    int seg  = l & 15;
    int rsub = l >> 4;

    float acc[8][4];
    #pragma unroll
    for (int nt = 0; nt < 8; nt++)
        #pragma unroll
        for (int i = 0; i < 4; i++) acc[nt][i] = 0.f;
    float sq[4];
    #pragma unroll
    for (int j = 0; j < 4; j++) sq[j] = 0.f;

    uint32_t smA0 = (uint32_t)__cvta_generic_to_shared(&Ah[0][0]);
    int mw = w & 7;                           // m-block for mma
    int arow_lm = mw*16 + (l & 7) + ((l >> 3) & 1) * 8;
    uint32_t a_off = (uint32_t)(arow_lm*144 + (l >> 4)*16);
    const uint2* fbase = (w >= 8) ? g_Wfrag : g_Bfrag;

    // prefetch chunk 0 (4 rows per thread)
    float4 R[4];
    #pragma unroll
    for (int j = 0; j < 4; j++)
        R[j] = *(const float4*)(rowp[w*8 + j*2 + rsub] + seg*4);

    for (int c = 0; c < 8; c++) {
        int buf = c & 1;
        // ---- convert prefetched rows into smem ----
        #pragma unroll
        for (int j = 0; j < 4; j++) {
            float4 v = R[j];
            sq[j] = fmaf(v.x, v.x, fmaf(v.y, v.y, fmaf(v.z, v.z, fmaf(v.w, v.w, sq[j]))));
            __half2 h01 = __floats2half2_rn(v.x, v.y);
            __half2 h23 = __floats2half2_rn(v.z, v.w);
            int row = w*8 + j*2 + rsub;
            *(uint2*)&Ah[buf][row*ASTRH + seg*4] =
                make_uint2(*(uint32_t*)&h01, *(uint32_t*)&h23);
        }
        __syncthreads();
        // ---- prefetch next chunk (hidden under mma phase) ----
        if (c < 7) {
            #pragma unroll
            for (int j = 0; j < 4; j++)
                R[j] = *(const float4*)(rowp[w*8 + j*2 + rsub] + (c+1)*64 + seg*4);
        }
        // ---- consume ----
        uint32_t smA = smA0 + (uint32_t)buf * 18432u;
        #pragma unroll
        for (int kc = 0; kc < 4; kc++) {
            uint32_t a[4];
            LDSM4(a, smA + a_off + kc*32);
            int c16 = c*4 + kc;
            const uint2* bp = fbase + (size_t)c16*256 + l;
            #pragma unroll
            for (int nt = 0; nt < 8; nt++) {
                uint2 b = __ldg(bp + nt*32);
                mma16816(acc[nt], a, (const uint32_t*)&b);
            }
        }
    }

    // ---- norms: reduce per-row squares over 16 seg lanes ----
    #pragma unroll
    for (int j = 0; j < 4; j++) {
        float s = sq[j];
        s += __shfl_xor_sync(0xffffffffu, s, 1);
        s += __shfl_xor_sync(0xffffffffu, s, 2);
        s += __shfl_xor_sync(0xffffffffu, s, 4);
        s += __shfl_xor_sync(0xffffffffu, s, 8);
        if (seg == 0) sqs[w*8 + j*2 + rsub] = s;
    }
    __syncthreads();   // sqs from all gather warps visible to G warps

    int arow = mw*16 + (l >> 2);
    int trow0 = t0 + arow;
    int col0  = (l & 3)*2;
    if (w < 8) {
        float inv0 = rsqrtf(sqs[arow]);
        float inv1 = rsqrtf(sqs[arow + 8]);
        #pragma unroll
        for (int nt = 0; nt < 8; nt++) {
            *(float2*)&g_G[(size_t)trow0*KK     + nt*8 + col0] =
                make_float2(acc[nt][0]*inv0, acc[nt][1]*inv0);
            *(float2*)&g_G[(size_t)(trow0+8)*KK + nt*8 + col0] =
                make_float2(acc[nt][2]*inv1, acc[nt][3]*inv1);
        }
    } else {
        #pragma unroll
        for (int nt = 0; nt < 8; nt++) {
            *(float2*)&g_VWx[(size_t)trow0*KK     + nt*8 + col0] =
                make_float2(acc[nt][0], acc[nt][1]);
            *(float2*)&g_VWx[(size_t)(trow0+8)*KK + nt*8 + col0] =
                make_float2(acc[nt][2], acc[nt][3]);
        }
    }
}

// ============================================================
// K2: 11-tap conv + bias + relu + max over K -> g_t[b,l]
// ============================================================
__global__ __launch_bounds__(256) void k_conv(const float* __restrict__ f1_w,
                                              const float* __restrict__ f1_b) {
    __shared__ float Gs[138*66];
    __shared__ float wsm[11];
    __shared__ float bias[64];
    int b  = blockIdx.y;
    int l0 = blockIdx.x * 128;
    int tid = threadIdx.x;
    if (tid < 11) wsm[tid] = f1_w[tid];
    if (tid < 64) bias[tid] = f1_b[tid];

    for (int idx = tid; idx < 138*16; idx += 256) {
        int row = idx >> 4, q = idx & 15;
        int l = l0 - 5 + row;
        float4 v = make_float4(0.f, 0.f, 0.f, 0.f);
        if ((unsigned)l < (unsigned)LL)
            v = *(const float4*)&g_G[((size_t)b*LL + l)*KK + q*4];
        int k0 = q*4;
        float vv[4] = {v.x, v.y, v.z, v.w};
        #pragma unroll
        for (int i = 0; i < 4; i++) {
            int k = k0 + i;
            Gs[row*66 + 2*(k & 31) + (k >> 5)] = vv[i];
        }
    }
    __syncthreads();

    float wreg[11];
    #pragma unroll
    for (int j = 0; j < 11; j++) wreg[j] = wsm[j];

    int lane = tid & 31;
    int kg = lane & 15;
    int lg = (tid >> 5)*2 + (lane >> 4);
    int L0 = lg * 8;

    float tmax[8];
    #pragma unroll
    for (int i = 0; i < 8; i++) tmax[i] = 0.f;

    #pragma unroll
    for (int kk = 0; kk < 4; kk++) {
        int k = kg + 16*kk;
        int cp = 2*(k & 31) + (k >> 5);
        float bk = bias[k];
        float win[18];
        #pragma unroll
        for (int m = 0; m < 18; m++) win[m] = Gs[(L0 + m)*66 + cp];
        #pragma unroll
        for (int i = 0; i < 8; i++) {
            float u = 0.f;
            #pragma unroll
            for (int j = 0; j < 11; j++) u = fmaf(wreg[j], win[i + j], u);
            tmax[i] = fmaxf(tmax[i], fmaxf(u + bk, 0.f));
        }
    }
    #pragma unroll
    for (int i = 0; i < 8; i++) {
        float t = tmax[i];
        t = fmaxf(t, __shfl_xor_sync(0xffffffffu, t, 1));
        t = fmaxf(t, __shfl_xor_sync(0xffffffffu, t, 2));
        t = fmaxf(t, __shfl_xor_sync(0xffffffffu, t, 4));
        t = fmaxf(t, __shfl_xor_sync(0xffffffffu, t, 8));
        if (kg == 0) g_t[(size_t)b*LL + l0 + L0 + i] = t;
    }
}

// ============================================================
// K3: single-pass softmax over L (folds 1/L)
// ============================================================
__global__ __launch_bounds__(512) void k_softmax() {
    int b = blockIdx.x;
    int tid = threadIdx.x;
    int wid = tid >> 5, lid = tid & 31;
    __shared__ float red[16], red2[16];

    float4 v = ((const float4*)(g_t + (size_t)b*LL))[tid];

    float mx = fmaxf(fmaxf(v.x, v.y), fmaxf(v.z, v.w));
    for (int o = 16; o; o >>= 1) mx = fmaxf(mx, __shfl_xor_sync(0xffffffffu, mx, o));
    if (lid == 0) red[wid] = mx;
    __syncthreads();
    if (wid == 0) {
        float m = red[lid & 15];
        for (int o = 8; o; o >>= 1) m = fmaxf(m, __shfl_xor_sync(0xffffffffu, m, o));
        if (lid == 0) red[0] = m;
    }
    __syncthreads();
    float m = red[0];

    float e0 = expf(v.x - m), e1 = expf(v.y - m), e2 = expf(v.z - m), e3 = expf(v.w - m);
    float s = e0 + e1 + e2 + e3;
    for (int o = 16; o; o >>= 1) s += __shfl_xor_sync(0xffffffffu, s, o);
    if (lid == 0) red2[wid] = s;
    __syncthreads();
    if (wid == 0) {
        float t = red2[lid & 15];
        for (int o = 8; o; o >>= 1) t += __shfl_xor_sync(0xffffffffu, t, o);
        if (lid == 0) red2[0] = t;
    }
    __syncthreads();
    float scale = 1.f / (red2[0] * (float)LL);

    ((float4*)(g_beta + (size_t)b*LL))[tid] =
        make_float4(e0*scale, e1*scale, e2*scale, e3*scale);
}

// ============================================================
// K4: out[b,k] += sum_l beta[b,l] * VWx[b*LL+l, k]   (coalesced)
// ============================================================
__global__ __launch_bounds__(128) void k_poolvwx(float* __restrict__ out) {
    __shared__ float4 red[128];
    int blk = blockIdx.x;
    int b = blk >> 4, c = blk & 15;
    int t = threadIdx.x;
    int i = t >> 4;
    int q = t & 15;
    int lbase = b*LL + c*128;

    float4 acc = make_float4(0.f, 0.f, 0.f, 0.f);
    #pragma unroll 4
    for (int it = 0; it < 16; it++) {
        int l = lbase + it*8 + i;
        float wgt = g_beta[l];
        float4 v = *(const float4*)&g_VWx[(size_t)l*KK + q*4];
        acc.x = fmaf(wgt, v.x, acc.x);
        acc.y = fmaf(wgt, v.y, acc.y);
        acc.z = fmaf(wgt, v.z, acc.z);
        acc.w = fmaf(wgt, v.w, acc.w);
    }
    red[t] = acc;
    __syncthreads();
    if (t < 64) {
        float4 o = red[t + 64];
        acc = red[t];
        acc.x += o.x; acc.y += o.y; acc.z += o.z; acc.w += o.w;
        red[t] = acc;
    }
    __syncthreads();
    if (t < 32) {
        float4 o = red[t + 32];
        acc = red[t];
        acc.x += o.x; acc.y += o.y; acc.z += o.z; acc.w += o.w;
        red[t] = acc;
    }
    __syncthreads();
    if (t < 16) {
        float4 o = red[t + 16];
        acc = red[t];
        acc.x += o.x; acc.y += o.y; acc.z += o.z; acc.w += o.w;
        atomicAdd(&out[b*KK + t*4 + 0], acc.x);
        atomicAdd(&out[b*KK + t*4 + 1], acc.y);
        atomicAdd(&out[b*KK + t*4 + 2], acc.z);
        atomicAdd(&out[b*KK + t*4 + 3], acc.w);
    }
}

// ============================================================
extern "C" void kernel_launch(void* const* d_in, const int* in_sizes, int n_in,
                              void* d_out, int out_size) {
    const int*   x   = (const int*)d_in[0];
    const float* V   = (const float*)d_in[1];
    const float* C   = (const float*)d_in[2];
    const float* f1w = (const float*)d_in[3];
    const float* f1b = (const float*)d_in[4];
    const float* f2w = (const float*)d_in[5];
    const float* f2b = (const float*)d_in[6];
    float* out = (float*)d_out;

    k_setup<<<KK, 256>>>(C, f2w, f2b, out);
    k_cosine<<<NT/128, 512>>>(x, V);
    k_conv<<<dim3(LL/128, BB), 256>>>(f1w, f1b);
    k_softmax<<<BB, 512>>>();
    k_poolvwx<<<BB*16, 128>>>(out);
}

// round 10
// speedup vs baseline: 2.4552x; 2.4552x over previous
#include <cuda_runtime.h>
#include <cuda_fp16.h>
#include <math.h>
#include <stdint.h>

#define BB 32
#define LL 2048
#define PP 512
#define KK 64
#define NT (BB*LL)   // 65536 tokens
#define VOCAB 50257

// ---- scratch (device globals: no allocation allowed) ----
__device__ __align__(16) float g_G[(size_t)NT*KK];     // cosine sims [token][k], 16 MB
__device__ float g_t[NT];                              // max-over-k pre-softmax
__device__ float g_beta[NT];                           // softmax weights (incl. 1/L)
__device__ __align__(16) float g_VW[(size_t)VOCAB*KK]; // V @ f2w^T, 12.9 MB
// fragments pre-baked into m16n8k16 B layout (fp16):
// [c16 (32)][ntile (8)][lane (32)] -> uint2 {b0, b1}
__device__ __align__(16) uint2 g_Bfrag[32*8*32];       // normalized centroids
__device__ __align__(16) uint2 g_Wfrag[32*8*32];       // f2_w

// ============================================================
// helpers
// ============================================================
__device__ __forceinline__ void mma16816(float* d, const uint32_t* a, const uint32_t* b) {
    asm volatile(
        "mma.sync.aligned.m16n8k16.row.col.f32.f16.f16.f32 "
        "{%0,%1,%2,%3}, {%4,%5,%6,%7}, {%8,%9}, {%0,%1,%2,%3};"
        : "+f"(d[0]), "+f"(d[1]), "+f"(d[2]), "+f"(d[3])
        : "r"(a[0]), "r"(a[1]), "r"(a[2]), "r"(a[3]), "r"(b[0]), "r"(b[1]));
}
#define LDSM4(r, addr) \
    asm volatile("ldmatrix.sync.aligned.m8n8.x4.shared.b16 {%0,%1,%2,%3}, [%4];" \
        : "=r"((r)[0]), "=r"((r)[1]), "=r"((r)[2]), "=r"((r)[3]) : "r"(addr))

// ============================================================
// K0: one-shot setup. CTA n (64): centroid-n inv norm, B/W fragments,
// out-bias init.
// ============================================================
__global__ __launch_bounds__(256) void k_setup(const float* __restrict__ C,
                                               const float* __restrict__ W,
                                               const float* __restrict__ f2b,
                                               float* __restrict__ out) {
    int n = blockIdx.x;
    int tid = threadIdx.x;
    __shared__ float ws[8];
    __shared__ float s_inv;

    float s = 0.f;
    for (int p = tid; p < PP; p += 256) { float v = C[n*PP + p]; s += v*v; }
    for (int o = 16; o; o >>= 1) s += __shfl_xor_sync(0xffffffffu, s, o);
    if ((tid & 31) == 0) ws[tid >> 5] = s;
    __syncthreads();
    if (tid == 0)
        s_inv = rsqrtf(ws[0]+ws[1]+ws[2]+ws[3]+ws[4]+ws[5]+ws[6]+ws[7]);
    __syncthreads();
    float inv = s_inv;

    // fragment positions owned by centroid n: item = c16*4 + j  (128 items)
    int nt = n >> 3;
    int lbase = (n & 7) * 4;
    for (int item = tid; item < 128; item += 256) {
        int c16 = item >> 2, j = item & 3;
        int k = c16*16 + j*2;
        int fidx = c16*256 + nt*32 + lbase + j;
        __half2 b0 = __floats2half2_rn(C[n*PP + k]     * inv, C[n*PP + k + 1] * inv);
        __half2 b1 = __floats2half2_rn(C[n*PP + k + 8] * inv, C[n*PP + k + 9] * inv);
        g_Bfrag[fidx] = make_uint2(*(uint32_t*)&b0, *(uint32_t*)&b1);
        __half2 w0 = __floats2half2_rn(W[n*PP + k],     W[n*PP + k + 1]);
        __half2 w1 = __floats2half2_rn(W[n*PP + k + 8], W[n*PP + k + 9]);
        g_Wfrag[fidx] = make_uint2(*(uint32_t*)&w0, *(uint32_t*)&w1);
    }
    // out init: 2048 total = 64 CTAs x 32
    if (tid < 32) out[n*32 + tid] = f2b[(n*32 + tid) & 63];
}

// ============================================================
// K1: gathered GEMM, fp16 single product, fp32 accum.
// CTA: 256 thr (8 warps), 128 tokens x 64 centroids, K=512 in 8 chunks of 64.
// (R7-measured version, unchanged)
// ============================================================
#define ASTRH 72   // fp16 row stride (144B)

__global__ __launch_bounds__(256) void k_cosine(const int* __restrict__ x,
                                                const float* __restrict__ V) {
    __shared__ __half Ah[2][128*ASTRH];        // 2 x 18432 B
    __shared__ const float* rowp[128];
    __shared__ float sqs[128];

    int tid = threadIdx.x;
    int w   = tid >> 5;
    int l   = tid & 31;
    int t0  = blockIdx.x * 128;

    if (tid < 128) rowp[tid] = V + (size_t)__ldg(&x[t0 + tid]) * PP;
    __syncthreads();

    int seg  = l & 15;
    int rsub = l >> 4;

    float acc[8][4];
    #pragma unroll
    for (int nt = 0; nt < 8; nt++)
        #pragma unroll
        for (int i = 0; i < 4; i++) acc[nt][i] = 0.f;
    float sq[8];
    #pragma unroll
    for (int j = 0; j < 8; j++) sq[j] = 0.f;

    uint32_t smA0 = (uint32_t)__cvta_generic_to_shared(&Ah[0][0]);
    int arow_lm = w*16 + (l & 7) + ((l >> 3) & 1) * 8;
    uint32_t a_off = (uint32_t)(arow_lm*144 + (l >> 4)*16);

    float4 R[8];
    #pragma unroll
    for (int j = 0; j < 8; j++)
        R[j] = *(const float4*)(rowp[w*16 + j*2 + rsub] + seg*4);

    for (int c = 0; c < 8; c++) {
        int buf = c & 1;
        #pragma unroll
        for (int j = 0; j < 8; j++) {
            float4 v = R[j];
            sq[j] = fmaf(v.x, v.x, fmaf(v.y, v.y, fmaf(v.z, v.z, fmaf(v.w, v.w, sq[j]))));
            __half2 h01 = __floats2half2_rn(v.x, v.y);
            __half2 h23 = __floats2half2_rn(v.z, v.w);
            int row = w*16 + j*2 + rsub;
            *(uint2*)&Ah[buf][row*ASTRH + seg*4] =
                make_uint2(*(uint32_t*)&h01, *(uint32_t*)&h23);
        }
        __syncthreads();
        if (c < 7) {
            #pragma unroll
            for (int j = 0; j < 8; j++)
                R[j] = *(const float4*)(rowp[w*16 + j*2 + rsub] + (c+1)*64 + seg*4);
        }
        uint32_t smA = smA0 + (uint32_t)buf * 18432u;
        #pragma unroll
        for (int kc = 0; kc < 4; kc++) {
            uint32_t a[4];
            LDSM4(a, smA + a_off + kc*32);
            int c16 = c*4 + kc;
            const uint2* bp = g_Bfrag + (size_t)c16*256 + l;
            #pragma unroll
            for (int nt = 0; nt < 8; nt++) {
                uint2 b = __ldg(bp + nt*32);
                mma16816(acc[nt], a, (const uint32_t*)&b);
            }
        }
    }

    #pragma unroll
    for (int j = 0; j < 8; j++) {
        float s = sq[j];
        s += __shfl_xor_sync(0xffffffffu, s, 1);
        s += __shfl_xor_sync(0xffffffffu, s, 2);
        s += __shfl_xor_sync(0xffffffffu, s, 4);
        s += __shfl_xor_sync(0xffffffffu, s, 8);
        if (seg == 0) sqs[w*16 + j*2 + rsub] = s;
    }
    __syncwarp();

    int arow = w*16 + (l >> 2);
    float inv0 = rsqrtf(sqs[arow]);
    float inv1 = rsqrtf(sqs[arow + 8]);
    int trow0 = t0 + arow;
    int col0  = (l & 3)*2;
    #pragma unroll
    for (int nt = 0; nt < 8; nt++) {
        float2 o0 = make_float2(acc[nt][0]*inv0, acc[nt][1]*inv0);
        float2 o1 = make_float2(acc[nt][2]*inv1, acc[nt][3]*inv1);
        *(float2*)&g_G[(size_t)trow0*KK     + nt*8 + col0] = o0;
        *(float2*)&g_G[(size_t)(trow0+8)*KK + nt*8 + col0] = o1;
    }
}

// ============================================================
// K1b: VW = V @ f2w^T  (coalesced rows, fp16 single product)
// (R7-measured version, unchanged)
// ============================================================
__global__ __launch_bounds__(256) void k_vw(const float* __restrict__ V) {
    __shared__ __half Ah[2][128*ASTRH];

    int tid = threadIdx.x;
    int w   = tid >> 5;
    int l   = tid & 31;
    int t0  = blockIdx.x * 128;

    int seg  = l & 15;
    int rsub = l >> 4;

    float acc[8][4];
    #pragma unroll
    for (int nt = 0; nt < 8; nt++)
        #pragma unroll
        for (int i = 0; i < 4; i++) acc[nt][i] = 0.f;

    uint32_t smA0 = (uint32_t)__cvta_generic_to_shared(&Ah[0][0]);
    int arow_lm = w*16 + (l & 7) + ((l >> 3) & 1) * 8;
    uint32_t a_off = (uint32_t)(arow_lm*144 + (l >> 4)*16);

    size_t vrow[8];
    #pragma unroll
    for (int j = 0; j < 8; j++) {
        int v = t0 + w*16 + j*2 + rsub;
        vrow[j] = (size_t)(v < VOCAB ? v : VOCAB-1) * PP;
    }

    float4 R[8];
    #pragma unroll
    for (int j = 0; j < 8; j++)
        R[j] = *(const float4*)(V + vrow[j] + seg*4);

    for (int c = 0; c < 8; c++) {
        int buf = c & 1;
        #pragma unroll
        for (int j = 0; j < 8; j++) {
            float4 v = R[j];
            __half2 h01 = __floats2half2_rn(v.x, v.y);
            __half2 h23 = __floats2half2_rn(v.z, v.w);
            int row = w*16 + j*2 + rsub;
            *(uint2*)&Ah[buf][row*ASTRH + seg*4] =
                make_uint2(*(uint32_t*)&h01, *(uint32_t*)&h23);
        }
        __syncthreads();
        if (c < 7) {
            #pragma unroll
            for (int j = 0; j < 8; j++)
                R[j] = *(const float4*)(V + vrow[j] + (c+1)*64 + seg*4);
        }
        uint32_t smA = smA0 + (uint32_t)buf * 18432u;
        #pragma unroll
        for (int kc = 0; kc < 4; kc++) {
            uint32_t a[4];
            LDSM4(a, smA + a_off + kc*32);
            int c16 = c*4 + kc;
            const uint2* bp = g_Wfrag + (size_t)c16*256 + l;
            #pragma unroll
            for (int nt = 0; nt < 8; nt++) {
                uint2 b = __ldg(bp + nt*32);
                mma16816(acc[nt], a, (const uint32_t*)&b);
            }
        }
    }

    int arow = w*16 + (l >> 2);
    int v0 = t0 + arow;
    int v1 = v0 + 8;
    int col0 = (l & 3)*2;
    #pragma unroll
    for (int nt = 0; nt < 8; nt++) {
        if (v0 < VOCAB)
            *(float2*)&g_VW[(size_t)v0*KK + nt*8 + col0] =
                make_float2(acc[nt][0], acc[nt][1]);
        if (v1 < VOCAB)
            *(float2*)&g_VW[(size_t)v1*KK + nt*8 + col0] =
                make_float2(acc[nt][2], acc[nt][3]);
    }
}

// ============================================================
// K2: 11-tap conv + bias + relu + max over K -> g_t[b,l]
// ============================================================
__global__ __launch_bounds__(256) void k_conv(const float* __restrict__ f1_w,
                                              const float* __restrict__ f1_b) {
    __shared__ float Gs[138*66];
    __shared__ float wsm[11];
    __shared__ float bias[64];
    int b  = blockIdx.y;
    int l0 = blockIdx.x * 128;
    int tid = threadIdx.x;
    if (tid < 11) wsm[tid] = f1_w[tid];
    if (tid < 64) bias[tid] = f1_b[tid];

    for (int idx = tid; idx < 138*16; idx += 256) {
        int row = idx >> 4, q = idx & 15;
        int l = l0 - 5 + row;
        float4 v = make_float4(0.f, 0.f, 0.f, 0.f);
        if ((unsigned)l < (unsigned)LL)
            v = *(const float4*)&g_G[((size_t)b*LL + l)*KK + q*4];
        int k0 = q*4;
        float vv[4] = {v.x, v.y, v.z, v.w};
        #pragma unroll
        for (int i = 0; i < 4; i++) {
            int k = k0 + i;
            Gs[row*66 + 2*(k & 31) + (k >> 5)] = vv[i];
        }
    }
    __syncthreads();

    float wreg[11];
    #pragma unroll
    for (int j = 0; j < 11; j++) wreg[j] = wsm[j];

    int lane = tid & 31;
    int kg = lane & 15;
    int lg = (tid >> 5)*2 + (lane >> 4);
    int L0 = lg * 8;

    float tmax[8];
    #pragma unroll
    for (int i = 0; i < 8; i++) tmax[i] = 0.f;

    #pragma unroll
    for (int kk = 0; kk < 4; kk++) {
        int k = kg + 16*kk;
        int cp = 2*(k & 31) + (k >> 5);
        float bk = bias[k];
        float win[18];
        #pragma unroll
        for (int m = 0; m < 18; m++) win[m] = Gs[(L0 + m)*66 + cp];
        #pragma unroll
        for (int i = 0; i < 8; i++) {
            float u = 0.f;
            #pragma unroll
            for (int j = 0; j < 11; j++) u = fmaf(wreg[j], win[i + j], u);
            tmax[i] = fmaxf(tmax[i], fmaxf(u + bk, 0.f));
        }
    }
    #pragma unroll
    for (int i = 0; i < 8; i++) {
        float t = tmax[i];
        t = fmaxf(t, __shfl_xor_sync(0xffffffffu, t, 1));
        t = fmaxf(t, __shfl_xor_sync(0xffffffffu, t, 2));
        t = fmaxf(t, __shfl_xor_sync(0xffffffffu, t, 4));
        t = fmaxf(t, __shfl_xor_sync(0xffffffffu, t, 8));
        if (kg == 0) g_t[(size_t)b*LL + l0 + L0 + i] = t;
    }
}

// ============================================================
// K3: single-pass softmax over L (folds 1/L)
// ============================================================
__global__ __launch_bounds__(512) void k_softmax() {
    int b = blockIdx.x;
    int tid = threadIdx.x;
    int wid = tid >> 5, lid = tid & 31;
    __shared__ float red[16], red2[16];

    float4 v = ((const float4*)(g_t + (size_t)b*LL))[tid];

    float mx = fmaxf(fmaxf(v.x, v.y), fmaxf(v.z, v.w));
    for (int o = 16; o; o >>= 1) mx = fmaxf(mx, __shfl_xor_sync(0xffffffffu, mx, o));
    if (lid == 0) red[wid] = mx;
    __syncthreads();
    if (wid == 0) {
        float m = red[lid & 15];
        for (int o = 8; o; o >>= 1) m = fmaxf(m, __shfl_xor_sync(0xffffffffu, m, o));
        if (lid == 0) red[0] = m;
    }
    __syncthreads();
    float m = red[0];

    float e0 = expf(v.x - m), e1 = expf(v.y - m), e2 = expf(v.z - m), e3 = expf(v.w - m);
    float s = e0 + e1 + e2 + e3;
    for (int o = 16; o; o >>= 1) s += __shfl_xor_sync(0xffffffffu, s, o);
    if (lid == 0) red2[wid] = s;
    __syncthreads();
    if (wid == 0) {
        float t = red2[lid & 15];
        for (int o = 8; o; o >>= 1) t += __shfl_xor_sync(0xffffffffu, t, o);
        if (lid == 0) red2[0] = t;
    }
    __syncthreads();
    float scale = 1.f / (red2[0] * (float)LL);

    ((float4*)(g_beta + (size_t)b*LL))[tid] =
        make_float4(e0*scale, e1*scale, e2*scale, e3*scale);
}

// ============================================================
// K4: out[b,k] += sum_l beta[b,l] * VW[x[b,l], k]
// ============================================================
__global__ __launch_bounds__(128) void k_poolvw(const int* __restrict__ x,
                                                float* __restrict__ out) {
    __shared__ float4 red[128];
    int blk = blockIdx.x;
    int b = blk >> 4, c = blk & 15;
    int t = threadIdx.x;
    int i = t >> 4;
    int q = t & 15;
    int lbase = b*LL + c*128;

    float4 acc = make_float4(0.f, 0.f, 0.f, 0.f);
    #pragma unroll 4
    for (int it = 0; it < 16; it++) {
        int l = it*8 + i;
        float wgt = g_beta[lbase + l];
        int row = __ldg(&x[lbase + l]);
        float4 v = *(const float4*)&g_VW[(size_t)row*KK + q*4];
        acc.x = fmaf(wgt, v.x, acc.x);
        acc.y = fmaf(wgt, v.y, acc.y);
        acc.z = fmaf(wgt, v.z, acc.z);
        acc.w = fmaf(wgt, v.w, acc.w);
    }
    red[t] = acc;
    __syncthreads();
    if (t < 64) {
        float4 o = red[t + 64];
        acc = red[t];
        acc.x += o.x; acc.y += o.y; acc.z += o.z; acc.w += o.w;
        red[t] = acc;
    }
    __syncthreads();
    if (t < 32) {
        float4 o = red[t + 32];
        acc = red[t];
        acc.x += o.x; acc.y += o.y; acc.z += o.z; acc.w += o.w;
        red[t] = acc;
    }
    __syncthreads();
    if (t < 16) {
        float4 o = red[t + 16];
        acc = red[t];
        acc.x += o.x; acc.y += o.y; acc.z += o.z; acc.w += o.w;
        atomicAdd(&out[b*KK + t*4 + 0], acc.x);
        atomicAdd(&out[b*KK + t*4 + 1], acc.y);
        atomicAdd(&out[b*KK + t*4 + 2], acc.z);
        atomicAdd(&out[b*KK + t*4 + 3], acc.w);
    }
}

// ============================================================
extern "C" void kernel_launch(void* const* d_in, const int* in_sizes, int n_in,
                              void* d_out, int out_size) {
    const int*   x   = (const int*)d_in[0];
    const float* V   = (const float*)d_in[1];
    const float* C   = (const float*)d_in[2];
    const float* f1w = (const float*)d_in[3];
    const float* f1b = (const float*)d_in[4];
    const float* f2w = (const float*)d_in[5];
    const float* f2b = (const float*)d_in[6];
    float* out = (float*)d_out;

    static cudaStream_t s2 = nullptr;
    static cudaEvent_t evA = nullptr, evB = nullptr;
    if (!s2) {
        cudaStreamCreateWithFlags(&s2, cudaStreamNonBlocking);
        cudaEventCreateWithFlags(&evA, cudaEventDisableTiming);
        cudaEventCreateWithFlags(&evB, cudaEventDisableTiming);
    }

    // serial: setup + the big gathered GEMM (sole owner of DRAM)
    k_setup<<<KK, 256>>>(C, f2w, f2b, out);
    k_cosine<<<NT/128, 256>>>(x, V);

    // fork: VW streams V while conv+softmax (G-resident) run on main
    cudaEventRecord(evA, 0);
    cudaStreamWaitEvent(s2, evA, 0);
    k_vw<<<(VOCAB + 127)/128, 256, 0, s2>>>(V);
    cudaEventRecord(evB, s2);

    k_conv<<<dim3(LL/128, BB), 256>>>(f1w, f1b);
    k_softmax<<<BB, 512>>>();

    // join + pooled gather into out
    cudaStreamWaitEvent(0, evB, 0);
    k_poolvw<<<BB*16, 128>>>(x, out);
}

// round 11
// speedup vs baseline: 2.8037x; 1.1419x over previous
#include <cuda_runtime.h>
#include <cuda_fp16.h>
#include <math.h>
#include <stdint.h>

#define BB 32
#define LL 2048
#define PP 512
#define KK 64
#define NT (BB*LL)   // 65536 tokens
#define VOCAB 50257

// ---- scratch (device globals: no allocation allowed) ----
__device__ float g_t[NT];                              // max-over-k pre-softmax
__device__ float g_beta[NT];                           // softmax weights (incl. 1/L)
__device__ float g_invn[VOCAB];                        // 1/||V_row||
__device__ __align__(16) float g_VC[(size_t)VOCAB*KK]; // V @ Chat^T, 12.9 MB
__device__ __align__(16) float g_VW[(size_t)VOCAB*KK]; // V @ f2w^T, 12.9 MB
// fragments pre-baked into m16n8k16 B layout (fp16):
// [c16 (32)][ntile (8)][lane (32)] -> uint2 {b0, b1}
__device__ __align__(16) uint2 g_Bfrag[32*8*32];       // normalized centroids
__device__ __align__(16) uint2 g_Wfrag[32*8*32];       // f2_w

// ============================================================
// helpers
// ============================================================
__device__ __forceinline__ void mma16816(float* d, const uint32_t* a, const uint32_t* b) {
    asm volatile(
        "mma.sync.aligned.m16n8k16.row.col.f32.f16.f16.f32 "
        "{%0,%1,%2,%3}, {%4,%5,%6,%7}, {%8,%9}, {%0,%1,%2,%3};"
        : "+f"(d[0]), "+f"(d[1]), "+f"(d[2]), "+f"(d[3])
        : "r"(a[0]), "r"(a[1]), "r"(a[2]), "r"(a[3]), "r"(b[0]), "r"(b[1]));
}
#define LDSM4(r, addr) \
    asm volatile("ldmatrix.sync.aligned.m8n8.x4.shared.b16 {%0,%1,%2,%3}, [%4];" \
        : "=r"((r)[0]), "=r"((r)[1]), "=r"((r)[2]), "=r"((r)[3]) : "r"(addr))

// ============================================================
// K0: one-shot setup. CTA n (64): centroid-n inv norm, B/W fragments,
// out-bias init.
// ============================================================
__global__ __launch_bounds__(256) void k_setup(const float* __restrict__ C,
                                               const float* __restrict__ W,
                                               const float* __restrict__ f2b,
                                               float* __restrict__ out) {
    int n = blockIdx.x;
    int tid = threadIdx.x;
    __shared__ float ws[8];
    __shared__ float s_inv;

    float s = 0.f;
    for (int p = tid; p < PP; p += 256) { float v = C[n*PP + p]; s += v*v; }
    for (int o = 16; o; o >>= 1) s += __shfl_xor_sync(0xffffffffu, s, o);
    if ((tid & 31) == 0) ws[tid >> 5] = s;
    __syncthreads();
    if (tid == 0)
        s_inv = rsqrtf(ws[0]+ws[1]+ws[2]+ws[3]+ws[4]+ws[5]+ws[6]+ws[7]);
    __syncthreads();
    float inv = s_inv;

    // fragment positions owned by centroid n: item = c16*4 + j  (128 items)
    int nt = n >> 3;
    int lbase = (n & 7) * 4;
    for (int item = tid; item < 128; item += 256) {
        int c16 = item >> 2, j = item & 3;
        int k = c16*16 + j*2;
        int fidx = c16*256 + nt*32 + lbase + j;
        __half2 b0 = __floats2half2_rn(C[n*PP + k]     * inv, C[n*PP + k + 1] * inv);
        __half2 b1 = __floats2half2_rn(C[n*PP + k + 8] * inv, C[n*PP + k + 9] * inv);
        g_Bfrag[fidx] = make_uint2(*(uint32_t*)&b0, *(uint32_t*)&b1);
        __half2 w0 = __floats2half2_rn(W[n*PP + k],     W[n*PP + k + 1]);
        __half2 w1 = __floats2half2_rn(W[n*PP + k + 8], W[n*PP + k + 9]);
        g_Wfrag[fidx] = make_uint2(*(uint32_t*)&w0, *(uint32_t*)&w1);
    }
    // out init: 2048 total = 64 CTAs x 32
    if (tid < 32) out[n*32 + tid] = f2b[(n*32 + tid) & 63];
}

// ============================================================
// K1: vocab GEMM pair. 786 CTAs = 393 row-tiles x 2.
// Even CTA: VC = V @ Chat^T + row norms.  Odd CTA: VW = V @ f2w^T.
// Both read the same 128 V rows (second reader hits L2).
// Body = proven k_vw structure (256 thr, 8 warps, K=512 in 8 chunks).
// ============================================================
#define ASTRH 72   // fp16 row stride (144B)

__global__ __launch_bounds__(256) void k_vocab(const float* __restrict__ V) {
    __shared__ __half Ah[2][128*ASTRH];

    int tid = threadIdx.x;
    int w   = tid >> 5;
    int l   = tid & 31;
    int isW = blockIdx.x & 1;
    int t0  = (blockIdx.x >> 1) * 128;

    int seg  = l & 15;
    int rsub = l >> 4;

    float acc[8][4];
    #pragma unroll
    for (int nt = 0; nt < 8; nt++)
        #pragma unroll
        for (int i = 0; i < 4; i++) acc[nt][i] = 0.f;
    float sq[8];
    #pragma unroll
    for (int j = 0; j < 8; j++) sq[j] = 0.f;

    uint32_t smA0 = (uint32_t)__cvta_generic_to_shared(&Ah[0][0]);
    int arow_lm = w*16 + (l & 7) + ((l >> 3) & 1) * 8;
    uint32_t a_off = (uint32_t)(arow_lm*144 + (l >> 4)*16);
    const uint2* fbase = isW ? g_Wfrag : g_Bfrag;

    size_t vrow[8];
    #pragma unroll
    for (int j = 0; j < 8; j++) {
        int v = t0 + w*16 + j*2 + rsub;
        vrow[j] = (size_t)(v < VOCAB ? v : VOCAB-1) * PP;
    }

    float4 R[8];
    #pragma unroll
    for (int j = 0; j < 8; j++)
        R[j] = *(const float4*)(V + vrow[j] + seg*4);

    for (int c = 0; c < 8; c++) {
        int buf = c & 1;
        #pragma unroll
        for (int j = 0; j < 8; j++) {
            float4 v = R[j];
            sq[j] = fmaf(v.x, v.x, fmaf(v.y, v.y, fmaf(v.z, v.z, fmaf(v.w, v.w, sq[j]))));
            __half2 h01 = __floats2half2_rn(v.x, v.y);
            __half2 h23 = __floats2half2_rn(v.z, v.w);
            int row = w*16 + j*2 + rsub;
            *(uint2*)&Ah[buf][row*ASTRH + seg*4] =
                make_uint2(*(uint32_t*)&h01, *(uint32_t*)&h23);
        }
        __syncthreads();
        if (c < 7) {
            #pragma unroll
            for (int j = 0; j < 8; j++)
                R[j] = *(const float4*)(V + vrow[j] + (c+1)*64 + seg*4);
        }
        uint32_t smA = smA0 + (uint32_t)buf * 18432u;
        #pragma unroll
        for (int kc = 0; kc < 4; kc++) {
            uint32_t a[4];
            LDSM4(a, smA + a_off + kc*32);
            int c16 = c*4 + kc;
            const uint2* bp = fbase + (size_t)c16*256 + l;
            #pragma unroll
            for (int nt = 0; nt < 8; nt++) {
                uint2 b = __ldg(bp + nt*32);
                mma16816(acc[nt], a, (const uint32_t*)&b);
            }
        }
    }

    // norms (even CTAs only): reduce per-row squares over 16 seg lanes
    if (!isW) {
        #pragma unroll
        for (int j = 0; j < 8; j++) {
            float s = sq[j];
            s += __shfl_xor_sync(0xffffffffu, s, 1);
            s += __shfl_xor_sync(0xffffffffu, s, 2);
            s += __shfl_xor_sync(0xffffffffu, s, 4);
            s += __shfl_xor_sync(0xffffffffu, s, 8);
            int v = t0 + w*16 + j*2 + rsub;
            if (seg == 0 && v < VOCAB) g_invn[v] = rsqrtf(s);
        }
    }

    float* dst = isW ? g_VW : g_VC;
    int arow = w*16 + (l >> 2);
    int v0 = t0 + arow;
    int v1 = v0 + 8;
    int col0 = (l & 3)*2;
    #pragma unroll
    for (int nt = 0; nt < 8; nt++) {
        if (v0 < VOCAB)
            *(float2*)&dst[(size_t)v0*KK + nt*8 + col0] =
                make_float2(acc[nt][0], acc[nt][1]);
        if (v1 < VOCAB)
            *(float2*)&dst[(size_t)v1*KK + nt*8 + col0] =
                make_float2(acc[nt][2], acc[nt][3]);
    }
}

// ============================================================
// K2: fused expand + 11-tap conv + bias + relu + max over K -> g_t[b,l]
// Tile loader gathers VC[x[b,l]] * invn[x[b,l]] (L2-resident table).
// ============================================================
__global__ __launch_bounds__(256) void k_conv(const int* __restrict__ x,
                                              const float* __restrict__ f1_w,
                                              const float* __restrict__ f1_b) {
    __shared__ float Gs[138*66];
    __shared__ float wsm[11];
    __shared__ float bias[64];
    int b  = blockIdx.y;
    int l0 = blockIdx.x * 128;
    int tid = threadIdx.x;
    if (tid < 11) wsm[tid] = f1_w[tid];
    if (tid < 64) bias[tid] = f1_b[tid];

    for (int idx = tid; idx < 138*16; idx += 256) {
        int row = idx >> 4, q = idx & 15;
        int l = l0 - 5 + row;
        float4 v = make_float4(0.f, 0.f, 0.f, 0.f);
        if ((unsigned)l < (unsigned)LL) {
            int tok = __ldg(&x[b*LL + l]);
            float inv = __ldg(&g_invn[tok]);
            v = *(const float4*)&g_VC[(size_t)tok*KK + q*4];
            v.x *= inv; v.y *= inv; v.z *= inv; v.w *= inv;
        }
        int k0 = q*4;
        float vv[4] = {v.x, v.y, v.z, v.w};
        #pragma unroll
        for (int i = 0; i < 4; i++) {
            int k = k0 + i;
            Gs[row*66 + 2*(k & 31) + (k >> 5)] = vv[i];
        }
    }
    __syncthreads();

    float wreg[11];
    #pragma unroll
    for (int j = 0; j < 11; j++) wreg[j] = wsm[j];

    int lane = tid & 31;
    int kg = lane & 15;
    int lg = (tid >> 5)*2 + (lane >> 4);
    int L0 = lg * 8;

    float tmax[8];
    #pragma unroll
    for (int i = 0; i < 8; i++) tmax[i] = 0.f;

    #pragma unroll
    for (int kk = 0; kk < 4; kk++) {
        int k = kg + 16*kk;
        int cp = 2*(k & 31) + (k >> 5);
        float bk = bias[k];
        float win[18];
        #pragma unroll
        for (int m = 0; m < 18; m++) win[m] = Gs[(L0 + m)*66 + cp];
        #pragma unroll
        for (int i = 0; i < 8; i++) {
            float u = 0.f;
            #pragma unroll
            for (int j = 0; j < 11; j++) u = fmaf(wreg[j], win[i + j], u);
            tmax[i] = fmaxf(tmax[i], fmaxf(u + bk, 0.f));
        }
    }
    #pragma unroll
    for (int i = 0; i < 8; i++) {
        float t = tmax[i];
        t = fmaxf(t, __shfl_xor_sync(0xffffffffu, t, 1));
        t = fmaxf(t, __shfl_xor_sync(0xffffffffu, t, 2));
        t = fmaxf(t, __shfl_xor_sync(0xffffffffu, t, 4));
        t = fmaxf(t, __shfl_xor_sync(0xffffffffu, t, 8));
        if (kg == 0) g_t[(size_t)b*LL + l0 + L0 + i] = t;
    }
}

// ============================================================
// K3: single-pass softmax over L (folds 1/L)
// ============================================================
__global__ __launch_bounds__(512) void k_softmax() {
    int b = blockIdx.x;
    int tid = threadIdx.x;
    int wid = tid >> 5, lid = tid & 31;
    __shared__ float red[16], red2[16];

    float4 v = ((const float4*)(g_t + (size_t)b*LL))[tid];

    float mx = fmaxf(fmaxf(v.x, v.y), fmaxf(v.z, v.w));
    for (int o = 16; o; o >>= 1) mx = fmaxf(mx, __shfl_xor_sync(0xffffffffu, mx, o));
    if (lid == 0) red[wid] = mx;
    __syncthreads();
    if (wid == 0) {
        float m = red[lid & 15];
        for (int o = 8; o; o >>= 1) m = fmaxf(m, __shfl_xor_sync(0xffffffffu, m, o));
        if (lid == 0) red[0] = m;
    }
    __syncthreads();
    float m = red[0];

    float e0 = expf(v.x - m), e1 = expf(v.y - m), e2 = expf(v.z - m), e3 = expf(v.w - m);
    float s = e0 + e1 + e2 + e3;
    for (int o = 16; o; o >>= 1) s += __shfl_xor_sync(0xffffffffu, s, o);
    if (lid == 0) red2[wid] = s;
    __syncthreads();
    if (wid == 0) {
        float t = red2[lid & 15];
        for (int o = 8; o; o >>= 1) t += __shfl_xor_sync(0xffffffffu, t, o);
        if (lid == 0) red2[0] = t;
    }
    __syncthreads();
    float scale = 1.f / (red2[0] * (float)LL);

    ((float4*)(g_beta + (size_t)b*LL))[tid] =
        make_float4(e0*scale, e1*scale, e2*scale, e3*scale);
}

// ============================================================
// K4: out[b,k] += sum_l beta[b,l] * VW[x[b,l], k]
// ============================================================
__global__ __launch_bounds__(128) void k_poolvw(const int* __restrict__ x,
                                                float* __restrict__ out) {
    __shared__ float4 red[128];
    int blk = blockIdx.x;
    int b = blk >> 4, c = blk & 15;
    int t = threadIdx.x;
    int i = t >> 4;
    int q = t & 15;
    int lbase = b*LL + c*128;

    float4 acc = make_float4(0.f, 0.f, 0.f, 0.f);
    #pragma unroll 4
    for (int it = 0; it < 16; it++) {
        int l = it*8 + i;
        float wgt = g_beta[lbase + l];
        int row = __ldg(&x[lbase + l]);
        float4 v = *(const float4*)&g_VW[(size_t)row*KK + q*4];
        acc.x = fmaf(wgt, v.x, acc.x);
        acc.y = fmaf(wgt, v.y, acc.y);
        acc.z = fmaf(wgt, v.z, acc.z);
        acc.w = fmaf(wgt, v.w, acc.w);
    }
    red[t] = acc;
    __syncthreads();
    if (t < 64) {
        float4 o = red[t + 64];
        acc = red[t];
        acc.x += o.x; acc.y += o.y; acc.z += o.z; acc.w += o.w;
        red[t] = acc;
    }
    __syncthreads();
    if (t < 32) {
        float4 o = red[t + 32];
        acc = red[t];
        acc.x += o.x; acc.y += o.y; acc.z += o.z; acc.w += o.w;
        red[t] = acc;
    }
    __syncthreads();
    if (t < 16) {
        float4 o = red[t + 16];
        acc = red[t];
        acc.x += o.x; acc.y += o.y; acc.z += o.z; acc.w += o.w;
        atomicAdd(&out[b*KK + t*4 + 0], acc.x);
        atomicAdd(&out[b*KK + t*4 + 1], acc.y);
        atomicAdd(&out[b*KK + t*4 + 2], acc.z);
        atomicAdd(&out[b*KK + t*4 + 3], acc.w);
    }
}

// ============================================================
extern "C" void kernel_launch(void* const* d_in, const int* in_sizes, int n_in,
                              void* d_out, int out_size) {
    const int*   x   = (const int*)d_in[0];
    const float* V   = (const float*)d_in[1];
    const float* C   = (const float*)d_in[2];
    const float* f1w = (const float*)d_in[3];
    const float* f1b = (const float*)d_in[4];
    const float* f2w = (const float*)d_in[5];
    const float* f2b = (const float*)d_in[6];
    float* out = (float*)d_out;

    k_setup<<<KK, 256>>>(C, f2w, f2b, out);
    k_vocab<<<((VOCAB + 127)/128)*2, 256>>>(V);
    k_conv<<<dim3(LL/128, BB), 256>>>(x, f1w, f1b);
    k_softmax<<<BB, 512>>>();
    k_poolvw<<<BB*16, 128>>>(x, out);
}

// round 12
// speedup vs baseline: 2.9649x; 1.0575x over previous
#include <cuda_runtime.h>
#include <cuda_fp16.h>
#include <math.h>
#include <stdint.h>

#define BB 32
#define LL 2048
#define PP 512
#define KK 64
#define NT (BB*LL)   // 65536 tokens
#define VOCAB 50257

// ---- scratch (device globals: no allocation allowed) ----
__device__ float g_t[NT];                               // max-over-k pre-softmax
__device__ float g_beta[NT];                            // softmax weights (incl. 1/L)
__device__ __align__(16) __half g_VCh[(size_t)VOCAB*KK]; // norm(V) @ Chat^T, fp16, 6.4 MB
__device__ __align__(16) __half g_VWh[(size_t)VOCAB*KK]; // V @ f2w^T, fp16, 6.4 MB
// fragments pre-baked into m16n8k16 B layout (fp16):
// [c16 (32)][ntile (8)][lane (32)] -> uint2 {b0, b1}
__device__ __align__(16) uint2 g_Bfrag[32*8*32];        // normalized centroids
__device__ __align__(16) uint2 g_Wfrag[32*8*32];        // f2_w

// ============================================================
// helpers
// ============================================================
__device__ __forceinline__ void mma16816(float* d, const uint32_t* a, const uint32_t* b) {
    asm volatile(
        "mma.sync.aligned.m16n8k16.row.col.f32.f16.f16.f32 "
        "{%0,%1,%2,%3}, {%4,%5,%6,%7}, {%8,%9}, {%0,%1,%2,%3};"
        : "+f"(d[0]), "+f"(d[1]), "+f"(d[2]), "+f"(d[3])
        : "r"(a[0]), "r"(a[1]), "r"(a[2]), "r"(a[3]), "r"(b[0]), "r"(b[1]));
}
#define LDSM4(r, addr) \
    asm volatile("ldmatrix.sync.aligned.m8n8.x4.shared.b16 {%0,%1,%2,%3}, [%4];" \
        : "=r"((r)[0]), "=r"((r)[1]), "=r"((r)[2]), "=r"((r)[3]) : "r"(addr))

__device__ __forceinline__ uint32_t packh2(float a, float b) {
    __half2 h = __floats2half2_rn(a, b);
    return *(uint32_t*)&h;
}

// ============================================================
// K0: one-shot setup. CTA n (64): centroid-n inv norm, B/W fragments,
// out-bias init.
// ============================================================
__global__ __launch_bounds__(256) void k_setup(const float* __restrict__ C,
                                               const float* __restrict__ W,
                                               const float* __restrict__ f2b,
                                               float* __restrict__ out) {
    int n = blockIdx.x;
    int tid = threadIdx.x;
    __shared__ float ws[8];
    __shared__ float s_inv;

    float s = 0.f;
    for (int p = tid; p < PP; p += 256) { float v = C[n*PP + p]; s += v*v; }
    for (int o = 16; o; o >>= 1) s += __shfl_xor_sync(0xffffffffu, s, o);
    if ((tid & 31) == 0) ws[tid >> 5] = s;
    __syncthreads();
    if (tid == 0)
        s_inv = rsqrtf(ws[0]+ws[1]+ws[2]+ws[3]+ws[4]+ws[5]+ws[6]+ws[7]);
    __syncthreads();
    float inv = s_inv;

    // fragment positions owned by centroid n: item = c16*4 + j  (128 items)
    int nt = n >> 3;
    int lbase = (n & 7) * 4;
    for (int item = tid; item < 128; item += 256) {
        int c16 = item >> 2, j = item & 3;
        int k = c16*16 + j*2;
        int fidx = c16*256 + nt*32 + lbase + j;
        g_Bfrag[fidx] = make_uint2(
            packh2(C[n*PP + k]     * inv, C[n*PP + k + 1] * inv),
            packh2(C[n*PP + k + 8] * inv, C[n*PP + k + 9] * inv));
        g_Wfrag[fidx] = make_uint2(
            packh2(W[n*PP + k],     W[n*PP + k + 1]),
            packh2(W[n*PP + k + 8], W[n*PP + k + 9]));
    }
    // out init: 2048 total = 64 CTAs x 32
    if (tid < 32) out[n*32 + tid] = f2b[(n*32 + tid) & 63];
}

// ============================================================
// K1: vocab GEMM pair. 786 CTAs = 393 row-tiles x 2.
// Even CTA: VCh = norm(V) @ Chat^T (invn folded).  Odd CTA: VWh = V @ f2w^T.
// Both read the same 128 V rows (second reader hits L2). fp16 table output.
// ============================================================
#define ASTRH 72   // fp16 row stride (144B)

__global__ __launch_bounds__(256) void k_vocab(const float* __restrict__ V) {
    __shared__ __half Ah[2][128*ASTRH];
    __shared__ float sqs[128];

    int tid = threadIdx.x;
    int w   = tid >> 5;
    int l   = tid & 31;
    int isW = blockIdx.x & 1;
    int t0  = (blockIdx.x >> 1) * 128;

    int seg  = l & 15;
    int rsub = l >> 4;

    float acc[8][4];
    #pragma unroll
    for (int nt = 0; nt < 8; nt++)
        #pragma unroll
        for (int i = 0; i < 4; i++) acc[nt][i] = 0.f;
    float sq[8];
    #pragma unroll
    for (int j = 0; j < 8; j++) sq[j] = 0.f;

    uint32_t smA0 = (uint32_t)__cvta_generic_to_shared(&Ah[0][0]);
    int arow_lm = w*16 + (l & 7) + ((l >> 3) & 1) * 8;
    uint32_t a_off = (uint32_t)(arow_lm*144 + (l >> 4)*16);
    const uint2* fbase = isW ? g_Wfrag : g_Bfrag;

    float4 R[8];
    #pragma unroll
    for (int j = 0; j < 8; j++) {
        int v = t0 + w*16 + j*2 + rsub;
        if (v >= VOCAB) v = VOCAB - 1;
        R[j] = *(const float4*)(V + (size_t)v*PP + seg*4);
    }

    for (int c = 0; c < 8; c++) {
        int buf = c & 1;
        #pragma unroll
        for (int j = 0; j < 8; j++) {
            float4 v = R[j];
            sq[j] = fmaf(v.x, v.x, fmaf(v.y, v.y, fmaf(v.z, v.z, fmaf(v.w, v.w, sq[j]))));
            int row = w*16 + j*2 + rsub;
            *(uint2*)&Ah[buf][row*ASTRH + seg*4] =
                make_uint2(packh2(v.x, v.y), packh2(v.z, v.w));
        }
        __syncthreads();
        if (c < 7) {
            #pragma unroll
            for (int j = 0; j < 8; j++) {
                int v = t0 + w*16 + j*2 + rsub;
                if (v >= VOCAB) v = VOCAB - 1;
                R[j] = *(const float4*)(V + (size_t)v*PP + (c+1)*64 + seg*4);
            }
        }
        uint32_t smA = smA0 + (uint32_t)buf * 18432u;
        #pragma unroll
        for (int kc = 0; kc < 4; kc++) {
            uint32_t a[4];
            LDSM4(a, smA + a_off + kc*32);
            int c16 = c*4 + kc;
            const uint2* bp = fbase + (size_t)c16*256 + l;
            #pragma unroll
            for (int nt = 0; nt < 8; nt++) {
                uint2 b = __ldg(bp + nt*32);
                mma16816(acc[nt], a, (const uint32_t*)&b);
            }
        }
    }

    // norms (even CTAs): reduce per-row squares, exchange within warp rows
    float inv0 = 1.f, inv1 = 1.f;
    int arow = w*16 + (l >> 2);
    if (!isW) {
        #pragma unroll
        for (int j = 0; j < 8; j++) {
            float s = sq[j];
            s += __shfl_xor_sync(0xffffffffu, s, 1);
            s += __shfl_xor_sync(0xffffffffu, s, 2);
            s += __shfl_xor_sync(0xffffffffu, s, 4);
            s += __shfl_xor_sync(0xffffffffu, s, 8);
            if (seg == 0) sqs[w*16 + j*2 + rsub] = s;
        }
        __syncwarp();
        inv0 = rsqrtf(sqs[arow]);
        inv1 = rsqrtf(sqs[arow + 8]);
    }

    __half* dst = isW ? g_VWh : g_VCh;
    int v0 = t0 + arow;
    int v1 = v0 + 8;
    int col0 = (l & 3)*2;
    #pragma unroll
    for (int nt = 0; nt < 8; nt++) {
        if (v0 < VOCAB)
            *(uint32_t*)&dst[(size_t)v0*KK + nt*8 + col0] =
                packh2(acc[nt][0]*inv0, acc[nt][1]*inv0);
        if (v1 < VOCAB)
            *(uint32_t*)&dst[(size_t)v1*KK + nt*8 + col0] =
                packh2(acc[nt][2]*inv1, acc[nt][3]*inv1);
    }
}

// ============================================================
// K2: fused expand + 11-tap conv + bias + relu + max over K -> g_t[b,l]
// Tile loader gathers VCh[x[b,l]] (fp16, L2-resident, invn pre-folded).
// ============================================================
__global__ __launch_bounds__(256) void k_conv(const int* __restrict__ x,
                                              const float* __restrict__ f1_w,
                                              const float* __restrict__ f1_b) {
    __shared__ float Gs[138*66];
    __shared__ float wsm[11];
    __shared__ float bias[64];
    int b  = blockIdx.y;
    int l0 = blockIdx.x * 128;
    int tid = threadIdx.x;
    if (tid < 11) wsm[tid] = f1_w[tid];
    if (tid < 64) bias[tid] = f1_b[tid];

    for (int idx = tid; idx < 138*16; idx += 256) {
        int row = idx >> 4, q = idx & 15;
        int l = l0 - 5 + row;
        float4 v = make_float4(0.f, 0.f, 0.f, 0.f);
        if ((unsigned)l < (unsigned)LL) {
            int tok = __ldg(&x[b*LL + l]);
            uint2 hv = *(const uint2*)&g_VCh[(size_t)tok*KK + q*4];
            float2 lo = __half22float2(*(__half2*)&hv.x);
            float2 hi = __half22float2(*(__half2*)&hv.y);
            v = make_float4(lo.x, lo.y, hi.x, hi.y);
        }
        int k0 = q*4;
        float vv[4] = {v.x, v.y, v.z, v.w};
        #pragma unroll
        for (int i = 0; i < 4; i++) {
            int k = k0 + i;
            Gs[row*66 + 2*(k & 31) + (k >> 5)] = vv[i];
        }
    }
    __syncthreads();

    float wreg[11];
    #pragma unroll
    for (int j = 0; j < 11; j++) wreg[j] = wsm[j];

    int lane = tid & 31;
    int kg = lane & 15;
    int lg = (tid >> 5)*2 + (lane >> 4);
    int L0 = lg * 8;

    float tmax[8];
    #pragma unroll
    for (int i = 0; i < 8; i++) tmax[i] = 0.f;

    #pragma unroll
    for (int kk = 0; kk < 4; kk++) {
        int k = kg + 16*kk;
        int cp = 2*(k & 31) + (k >> 5);
        float bk = bias[k];
        float win[18];
        #pragma unroll
        for (int m = 0; m < 18; m++) win[m] = Gs[(L0 + m)*66 + cp];
        #pragma unroll
        for (int i = 0; i < 8; i++) {
            float u = 0.f;
            #pragma unroll
            for (int j = 0; j < 11; j++) u = fmaf(wreg[j], win[i + j], u);
            tmax[i] = fmaxf(tmax[i], fmaxf(u + bk, 0.f));
        }
    }
    #pragma unroll
    for (int i = 0; i < 8; i++) {
        float t = tmax[i];
        t = fmaxf(t, __shfl_xor_sync(0xffffffffu, t, 1));
        t = fmaxf(t, __shfl_xor_sync(0xffffffffu, t, 2));
        t = fmaxf(t, __shfl_xor_sync(0xffffffffu, t, 4));
        t = fmaxf(t, __shfl_xor_sync(0xffffffffu, t, 8));
        if (kg == 0) g_t[(size_t)b*LL + l0 + L0 + i] = t;
    }
}

// ============================================================
// K3: single-pass softmax over L (folds 1/L)
// ============================================================
__global__ __launch_bounds__(512) void k_softmax() {
    int b = blockIdx.x;
    int tid = threadIdx.x;
    int wid = tid >> 5, lid = tid & 31;
    __shared__ float red[16], red2[16];

    float4 v = ((const float4*)(g_t + (size_t)b*LL))[tid];

    float mx = fmaxf(fmaxf(v.x, v.y), fmaxf(v.z, v.w));
    for (int o = 16; o; o >>= 1) mx = fmaxf(mx, __shfl_xor_sync(0xffffffffu, mx, o));
    if (lid == 0) red[wid] = mx;
    __syncthreads();
    if (wid == 0) {
        float m = red[lid & 15];
        for (int o = 8; o; o >>= 1) m = fmaxf(m, __shfl_xor_sync(0xffffffffu, m, o));
        if (lid == 0) red[0] = m;
    }
    __syncthreads();
    float m = red[0];

    float e0 = expf(v.x - m), e1 = expf(v.y - m), e2 = expf(v.z - m), e3 = expf(v.w - m);
    float s = e0 + e1 + e2 + e3;
    for (int o = 16; o; o >>= 1) s += __shfl_xor_sync(0xffffffffu, s, o);
    if (lid == 0) red2[wid] = s;
    __syncthreads();
    if (wid == 0) {
        float t = red2[lid & 15];
        for (int o = 8; o; o >>= 1) t += __shfl_xor_sync(0xffffffffu, t, o);
        if (lid == 0) red2[0] = t;
    }
    __syncthreads();
    float scale = 1.f / (red2[0] * (float)LL);

    ((float4*)(g_beta + (size_t)b*LL))[tid] =
        make_float4(e0*scale, e1*scale, e2*scale, e3*scale);
}

// ============================================================
// K4: out[b,k] += sum_l beta[b,l] * VWh[x[b,l], k]   (fp16 table)
// ============================================================
__global__ __launch_bounds__(128) void k_poolvw(const int* __restrict__ x,
                                                float* __restrict__ out) {
    __shared__ float4 red[128];
    int blk = blockIdx.x;
    int b = blk >> 4, c = blk & 15;
    int t = threadIdx.x;
    int i = t >> 4;
    int q = t & 15;
    int lbase = b*LL + c*128;

    float4 acc = make_float4(0.f, 0.f, 0.f, 0.f);
    #pragma unroll 4
    for (int it = 0; it < 16; it++) {
        int l = it*8 + i;
        float wgt = g_beta[lbase + l];
        int row = __ldg(&x[lbase + l]);
        uint2 hv = *(const uint2*)&g_VWh[(size_t)row*KK + q*4];
        float2 lo = __half22float2(*(__half2*)&hv.x);
        float2 hi = __half22float2(*(__half2*)&hv.y);
        acc.x = fmaf(wgt, lo.x, acc.x);
        acc.y = fmaf(wgt, lo.y, acc.y);
        acc.z = fmaf(wgt, hi.x, acc.z);
        acc.w = fmaf(wgt, hi.y, acc.w);
    }
    red[t] = acc;
    __syncthreads();
    if (t < 64) {
        float4 o = red[t + 64];
        acc = red[t];
        acc.x += o.x; acc.y += o.y; acc.z += o.z; acc.w += o.w;
        red[t] = acc;
    }
    __syncthreads();
    if (t < 32) {
        float4 o = red[t + 32];
        acc = red[t];
        acc.x += o.x; acc.y += o.y; acc.z += o.z; acc.w += o.w;
        red[t] = acc;
    }
    __syncthreads();
    if (t < 16) {
        float4 o = red[t + 16];
        acc = red[t];
        acc.x += o.x; acc.y += o.y; acc.z += o.z; acc.w += o.w;
        atomicAdd(&out[b*KK + t*4 + 0], acc.x);
        atomicAdd(&out[b*KK + t*4 + 1], acc.y);
        atomicAdd(&out[b*KK + t*4 + 2], acc.z);
        atomicAdd(&out[b*KK + t*4 + 3], acc.w);
    }
}

// ============================================================
extern "C" void kernel_launch(void* const* d_in, const int* in_sizes, int n_in,
                              void* d_out, int out_size) {
    const int*   x   = (const int*)d_in[0];
    const float* V   = (const float*)d_in[1];
    const float* C   = (const float*)d_in[2];
    const float* f1w = (const float*)d_in[3];
    const float* f1b = (const float*)d_in[4];
    const float* f2w = (const float*)d_in[5];
    const float* f2b = (const float*)d_in[6];
    float* out = (float*)d_out;

    k_setup<<<KK, 256>>>(C, f2w, f2b, out);
    k_vocab<<<((VOCAB + 127)/128)*2, 256>>>(V);
    k_conv<<<dim3(LL/128, BB), 256>>>(x, f1w, f1b);
    k_softmax<<<BB, 512>>>();
    k_poolvw<<<BB*16, 128>>>(x, out);
}